// round 2
// baseline (speedup 1.0000x reference)
#include <cuda_runtime.h>
#include <cuda_fp16.h>
#include <stdint.h>

// Fused int8-dequant linear: out[m][n] = sum_k x[m][k] * (f16(wq[n][k]) * f16(scale[n])) + bias[n]
// Harness dtypes: x f32, weight_q i32, scale f32, bias f32, out f32.
// M=2048, N=11008, K=4096. Tensor-core fp16 MMA (m16n8k16), fp32 accumulation.

#define BM 128
#define BN 128
#define BK 32
#define PADK (BK + 8)   // 40-half stride -> conflict-free fragment LDS
#define NTHREADS 256

__device__ __forceinline__ void mma16816(float d[4], const uint32_t a[4], const uint32_t b[2]) {
    asm volatile(
        "mma.sync.aligned.m16n8k16.row.col.f32.f16.f16.f32 "
        "{%0,%1,%2,%3}, {%4,%5,%6,%7}, {%8,%9}, {%0,%1,%2,%3};\n"
        : "+f"(d[0]), "+f"(d[1]), "+f"(d[2]), "+f"(d[3])
        : "r"(a[0]), "r"(a[1]), "r"(a[2]), "r"(a[3]), "r"(b[0]), "r"(b[1]));
}

__global__ __launch_bounds__(NTHREADS)
void qlinear_kernel(const float* __restrict__ x,
                    const int*   __restrict__ wq,
                    const float* __restrict__ scale,
                    const float* __restrict__ bias,
                    float* __restrict__ out,
                    int M, int N, int K)
{
    __shared__ __half As[2][BM][PADK];
    __shared__ __half Bs[2][BN][PADK];

    const int tid  = threadIdx.x;
    const int lane = tid & 31;
    const int warp = tid >> 5;
    const int wm   = (warp >> 1) * 32;   // warp M offset: 0,32,64,96
    const int wn   = (warp & 1) * 64;    // warp N offset: 0,64
    const int lr   = lane >> 2;          // 0..7
    const int lc   = (lane & 3) * 2;     // 0,2,4,6

    const int m0 = blockIdx.y * BM;
    const int n0 = blockIdx.x * BN;

    // ---- global load mapping ----
    // A (f32): thread covers rows a_row, a_row+64; 8 floats starting at a_col
    const int a_row = tid >> 2;          // 0..63
    const int a_col = (tid & 3) * 8;     // 0,8,16,24
    // B (i32): thread covers row b_row; 16 ints starting at b_col
    const int b_row = tid >> 1;          // 0..127
    const int b_col = (tid & 1) * 16;    // 0,16

    // per-output-channel scale as f16 (exact: data originated as f16)
    const __half ws = __float2half_rn(scale[n0 + b_row]);

    const int ktiles = K / BK;

    float acc[2][8][4];
#pragma unroll
    for (int i = 0; i < 2; i++)
#pragma unroll
        for (int j = 0; j < 8; j++)
#pragma unroll
            for (int c = 0; c < 4; c++) acc[i][j][c] = 0.f;

    const int gm0 = m0 + a_row;
    const int gm1 = gm0 + 64;
    const float* xp0 = x + (size_t)gm0 * K + a_col;
    const float* xp1 = x + (size_t)gm1 * K + a_col;
    const int*   bp  = wq + (size_t)(n0 + b_row) * K + b_col;

    float4 av[2][2];    // 2 rows x 8 floats
    int4   bv[4];       // 16 ints

    // ---- prologue: load tile 0 into registers ----
    av[0][0] = *(const float4*)(xp0);
    av[0][1] = *(const float4*)(xp0 + 4);
    av[1][0] = *(const float4*)(xp1);
    av[1][1] = *(const float4*)(xp1 + 4);
#pragma unroll
    for (int i = 0; i < 4; i++) bv[i] = *(const int4*)(bp + i * 4);

    // ---- convert + store tile 0 ----
    {
        __half ah[2][8];
#pragma unroll
        for (int r = 0; r < 2; r++) {
            const float* f = (const float*)&av[r][0];
#pragma unroll
            for (int i = 0; i < 8; i++) ah[r][i] = __float2half_rn(f[i]);
        }
        *(uint4*)&As[0][a_row][a_col]      = *(uint4*)&ah[0][0];
        *(uint4*)&As[0][a_row + 64][a_col] = *(uint4*)&ah[1][0];

        const int* pb = (const int*)&bv[0];
        __half bh[16];
#pragma unroll
        for (int i = 0; i < 16; i++)
            bh[i] = __hmul(__int2half_rn(pb[i]), ws);
        *(uint4*)&Bs[0][b_row][b_col]     = *(uint4*)&bh[0];
        *(uint4*)&Bs[0][b_row][b_col + 8] = *(uint4*)&bh[8];
    }
    __syncthreads();

    for (int kt = 0; kt < ktiles; kt++) {
        const int cur = kt & 1;
        const int nxt = cur ^ 1;

        // ---- prefetch next tile into registers ----
        if (kt + 1 < ktiles) {
            const size_t koff = (size_t)(kt + 1) * BK;
            av[0][0] = *(const float4*)(xp0 + koff);
            av[0][1] = *(const float4*)(xp0 + koff + 4);
            av[1][0] = *(const float4*)(xp1 + koff);
            av[1][1] = *(const float4*)(xp1 + koff + 4);
#pragma unroll
            for (int i = 0; i < 4; i++) bv[i] = *(const int4*)(bp + koff + i * 4);
        }

        // ---- compute on current buffer ----
#pragma unroll
        for (int ks = 0; ks < 2; ks++) {
            const int kk = ks * 16;
            uint32_t afrag[2][4];
            uint32_t bfrag[8][2];
#pragma unroll
            for (int mt = 0; mt < 2; mt++) {
                const int r = wm + mt * 16 + lr;
                afrag[mt][0] = *(const uint32_t*)&As[cur][r][kk + lc];
                afrag[mt][1] = *(const uint32_t*)&As[cur][r + 8][kk + lc];
                afrag[mt][2] = *(const uint32_t*)&As[cur][r][kk + lc + 8];
                afrag[mt][3] = *(const uint32_t*)&As[cur][r + 8][kk + lc + 8];
            }
#pragma unroll
            for (int nt = 0; nt < 8; nt++) {
                const int r = wn + nt * 8 + lr;
                bfrag[nt][0] = *(const uint32_t*)&Bs[cur][r][kk + lc];
                bfrag[nt][1] = *(const uint32_t*)&Bs[cur][r][kk + lc + 8];
            }
#pragma unroll
            for (int mt = 0; mt < 2; mt++)
#pragma unroll
                for (int nt = 0; nt < 8; nt++)
                    mma16816(acc[mt][nt], afrag[mt], bfrag[nt]);
        }

        // ---- convert + store prefetched tile into next buffer ----
        if (kt + 1 < ktiles) {
            __half ah[2][8];
#pragma unroll
            for (int r = 0; r < 2; r++) {
                const float* f = (const float*)&av[r][0];
#pragma unroll
                for (int i = 0; i < 8; i++) ah[r][i] = __float2half_rn(f[i]);
            }
            *(uint4*)&As[nxt][a_row][a_col]      = *(uint4*)&ah[0][0];
            *(uint4*)&As[nxt][a_row + 64][a_col] = *(uint4*)&ah[1][0];

            const int* pb = (const int*)&bv[0];
            __half bh[16];
#pragma unroll
            for (int i = 0; i < 16; i++)
                bh[i] = __hmul(__int2half_rn(pb[i]), ws);
            *(uint4*)&Bs[nxt][b_row][b_col]     = *(uint4*)&bh[0];
            *(uint4*)&Bs[nxt][b_row][b_col + 8] = *(uint4*)&bh[8];
        }
        __syncthreads();
    }

    // ---- epilogue: emulate reference rounding: h = f16(acc); h += f16(bias); out = f32(h) ----
#pragma unroll
    for (int mt = 0; mt < 2; mt++) {
        const int row0 = m0 + wm + mt * 16 + lr;
        const int row1 = row0 + 8;
#pragma unroll
        for (int nt = 0; nt < 8; nt++) {
            const int col = n0 + wn + nt * 8 + lc;
            const __half bh0 = __float2half_rn(bias[col]);
            const __half bh1 = __float2half_rn(bias[col + 1]);

            __half h00 = __hadd(__float2half_rn(acc[mt][nt][0]), bh0);
            __half h01 = __hadd(__float2half_rn(acc[mt][nt][1]), bh1);
            __half h10 = __hadd(__float2half_rn(acc[mt][nt][2]), bh0);
            __half h11 = __hadd(__float2half_rn(acc[mt][nt][3]), bh1);

            float2 v0 = make_float2(__half2float(h00), __half2float(h01));
            float2 v1 = make_float2(__half2float(h10), __half2float(h11));
            if (row0 < M) *(float2*)&out[(size_t)row0 * N + col] = v0;
            if (row1 < M) *(float2*)&out[(size_t)row1 * N + col] = v1;
        }
    }
}

extern "C" void kernel_launch(void* const* d_in, const int* in_sizes, int n_in,
                              void* d_out, int out_size)
{
    const float* x     = (const float*)d_in[0];
    const int*   wq    = (const int*)d_in[1];
    const float* scale = (const float*)d_in[2];
    const float* bias  = (const float*)d_in[3];
    float*       out   = (float*)d_out;

    const int N = in_sizes[3];              // 11008 (bias length = out features)
    const int K = in_sizes[1] / N;          // 4096
    const int M = in_sizes[0] / K;          // 2048 = B*S

    dim3 grid(N / BN, (M + BM - 1) / BM);
    qlinear_kernel<<<grid, NTHREADS>>>(x, wq, scale, bias, out, M, N, K);
}

// round 4
// speedup vs baseline: 2.5433x; 2.5433x over previous
#include <cuda_runtime.h>
#include <cuda_fp16.h>
#include <stdint.h>

// ===================================================================
// Fused int8-dequant linear (sm_103 base ISA: no tcgen05).
//   out[m][n] = f32( f16( sum_k f16(x[m][k]) * (f16(wq[n][k])*f16(scale[n])) ) + f16(bias[n]) )
// Harness dtypes: x f32, weight_q i32, scale f32, bias f32, out f32.
// M=2048, N=11008, K=4096.
//
// Stage 1: prep kernels dequant W -> f16 and convert x -> f16 into
//   __device__ scratch, blocked as 16KB tiles [128 rows x 64 halves],
//   SW128-swizzled, so the GEMM loads each tile with ONE cp.async.bulk.
// Stage 2: GEMM, CTA tile 128x256, K-chunk 64, 4-stage mbarrier pipeline
//   (cp.async.bulk producer, single thread), ldmatrix.x4 fragment loads,
//   mma.sync.m16n8k16 f16->f32, warp tile 64x64 (8 warps, 2x4).
// ===================================================================

#define NTILE_MAX 86                 // 11008/128
#define MTILE_MAX 16                 // 2048/128
#define KTILES_MAX 64                // 4096/64

__device__ __half g_wf16[(size_t)NTILE_MAX * KTILES_MAX * 8192];
__device__ __half g_xf16[(size_t)MTILE_MAX * KTILES_MAX * 8192];

// ------------------------- PTX helpers -----------------------------
__device__ __forceinline__ uint32_t smem_u32(const void* p) {
    uint32_t a;
    asm("{ .reg .u64 t; cvta.to.shared.u64 t, %1; cvt.u32.u64 %0, t; }" : "=r"(a) : "l"(p));
    return a;
}

#define MBAR_INIT(addr, cnt) \
    asm volatile("mbarrier.init.shared.b64 [%0], %1;" :: "r"(addr), "r"(cnt) : "memory")

#define MBAR_EXPECT_TX(addr, bytes) \
    asm volatile("mbarrier.arrive.expect_tx.shared.b64 _, [%0], %1;" :: "r"(addr), "r"(bytes) : "memory")

#define MBAR_WAIT(addr, ph) do {                                            \
    uint32_t _mb = (addr); uint32_t _p = (ph); uint32_t _done;              \
    asm volatile("{\n\t.reg .pred p;\n\t"                                   \
        "mbarrier.try_wait.parity.acquire.cta.shared::cta.b64 p, [%1], %2;\n\t" \
        "selp.b32 %0, 1, 0, p;\n\t}"                                        \
        : "=r"(_done) : "r"(_mb), "r"(_p) : "memory");                      \
    if (!_done) {                                                           \
        asm volatile("{\n\t.reg .pred P1;\n\t"                              \
            "WL_%=:\n\t"                                                    \
            "mbarrier.try_wait.parity.acquire.cta.shared::cta.b64 P1, [%0], %1, 0x989680;\n\t" \
            "@P1 bra.uni WD_%=;\n\t"                                        \
            "bra.uni WL_%=;\n\t"                                            \
            "WD_%=:\n\t}" :: "r"(_mb), "r"(_p) : "memory");                 \
    }                                                                       \
} while (0)

__device__ __forceinline__ void bulk_g2s(uint32_t dst, const void* src, uint32_t bytes, uint32_t mbar) {
    asm volatile(
        "cp.async.bulk.shared::cta.global.mbarrier::complete_tx::bytes [%0], [%1], %2, [%3];"
        :: "r"(dst), "l"(src), "r"(bytes), "r"(mbar) : "memory");
}

__device__ __forceinline__ void ldsm_x4(uint32_t r[4], uint32_t addr) {
    asm volatile("ldmatrix.sync.aligned.m8n8.x4.shared.b16 {%0,%1,%2,%3}, [%4];"
        : "=r"(r[0]), "=r"(r[1]), "=r"(r[2]), "=r"(r[3]) : "r"(addr));
}

__device__ __forceinline__ void mma16816(float d[4], const uint32_t a[4], const uint32_t b[2]) {
    asm volatile(
        "mma.sync.aligned.m16n8k16.row.col.f32.f16.f16.f32 "
        "{%0,%1,%2,%3}, {%4,%5,%6,%7}, {%8,%9}, {%0,%1,%2,%3};\n"
        : "+f"(d[0]), "+f"(d[1]), "+f"(d[2]), "+f"(d[3])
        : "r"(a[0]), "r"(a[1]), "r"(a[2]), "r"(a[3]), "r"(b[0]), "r"(b[1]));
}

__device__ __forceinline__ uint32_t sw128(uint32_t byte_off) {
    return byte_off ^ ((byte_off >> 3) & 0x70);
}

// ------------------------- prep kernels ----------------------------
// One thread per 8 halves (uint4). Scratch layout: 16KB tiles,
//   blk = row_tile * ktiles + k_tile; within: [r 0..127][64 halves], SW128.

__global__ __launch_bounds__(256)
void prep_w(const int* __restrict__ wq, const float* __restrict__ scale,
            int K, long total_groups)
{
    long idx = (long)blockIdx.x * blockDim.x + threadIdx.x;
    if (idx >= total_groups) return;
    int grp = (int)(idx & 1023);
    long blk = idx >> 10;
    int ktiles = K >> 6;
    int k_tile = (int)(blk % ktiles);
    int n_tile = (int)(blk / ktiles);
    int r  = grp >> 3;
    int c8 = grp & 7;
    int n = n_tile * 128 + r;
    int k = k_tile * 64 + c8 * 8;

    const int4* p = (const int4*)(wq + (size_t)n * K + k);
    int4 w0 = p[0], w1 = p[1];
    __half s = __float2half_rn(scale[n]);
    __half h[8];
    h[0] = __hmul(__int2half_rn(w0.x), s);
    h[1] = __hmul(__int2half_rn(w0.y), s);
    h[2] = __hmul(__int2half_rn(w0.z), s);
    h[3] = __hmul(__int2half_rn(w0.w), s);
    h[4] = __hmul(__int2half_rn(w1.x), s);
    h[5] = __hmul(__int2half_rn(w1.y), s);
    h[6] = __hmul(__int2half_rn(w1.z), s);
    h[7] = __hmul(__int2half_rn(w1.w), s);

    uint32_t off = sw128((uint32_t)(r * 128 + c8 * 16));
    *(uint4*)((char*)g_wf16 + blk * 16384 + off) = *(uint4*)h;
}

__global__ __launch_bounds__(256)
void prep_x(const float* __restrict__ x, int K, long total_groups)
{
    long idx = (long)blockIdx.x * blockDim.x + threadIdx.x;
    if (idx >= total_groups) return;
    int grp = (int)(idx & 1023);
    long blk = idx >> 10;
    int ktiles = K >> 6;
    int k_tile = (int)(blk % ktiles);
    int m_tile = (int)(blk / ktiles);
    int r  = grp >> 3;
    int c8 = grp & 7;
    int m = m_tile * 128 + r;
    int k = k_tile * 64 + c8 * 8;

    const float4* p = (const float4*)(x + (size_t)m * K + k);
    float4 f0 = p[0], f1 = p[1];
    __half h[8];
    h[0] = __float2half_rn(f0.x); h[1] = __float2half_rn(f0.y);
    h[2] = __float2half_rn(f0.z); h[3] = __float2half_rn(f0.w);
    h[4] = __float2half_rn(f1.x); h[5] = __float2half_rn(f1.y);
    h[6] = __float2half_rn(f1.z); h[7] = __float2half_rn(f1.w);

    uint32_t off = sw128((uint32_t)(r * 128 + c8 * 16));
    *(uint4*)((char*)g_xf16 + blk * 16384 + off) = *(uint4*)h;
}

// ------------------------- GEMM kernel -----------------------------
// CTA: 128 (M) x 256 (N), BK=64. 8 warps as 2 (M) x 4 (N), warp tile 64x64.
#define NSTAGES 4
#define TILE_B 16384
#define STAGE_BYTES (3 * TILE_B)       // A(16K) + B0(16K) + B1(16K)
#define CTRL 1024
#define GEMM_SMEM (CTRL + NSTAGES * STAGE_BYTES)   // 197632

__global__ __launch_bounds__(256, 1)
void qgemm(const float* __restrict__ bias, float* __restrict__ out,
           int M, int N, int K)
{
    extern __shared__ __align__(1024) char smem[];
    const uint32_t sb = smem_u32(smem);
    const int tid  = threadIdx.x;
    const int lid  = tid & 31;
    const int warp = tid >> 5;
    const int wm   = (warp >> 2) * 64;     // 0,64
    const int wn   = (warp & 3) * 64;      // 0,64,128,192

    const int bx = blockIdx.x;             // N block (256)
    const int by = blockIdx.y;             // M block (128)
    const int ktiles = K >> 6;
    const int m0 = by * 128;
    const int n0 = bx * 256;

    if (tid == 0) {
        for (int s = 0; s < NSTAGES; s++) MBAR_INIT(sb + s * 8, 1);
    }
    __syncthreads();

    const char* Ag  = (const char*)g_xf16 + (size_t)by * ktiles * TILE_B;
    const char* B0g = (const char*)g_wf16 + (size_t)(2 * bx)     * ktiles * TILE_B;
    const char* B1g = (const char*)g_wf16 + (size_t)(2 * bx + 1) * ktiles * TILE_B;

    // prologue: fill all stages
    if (tid == 0) {
#pragma unroll
        for (int s = 0; s < NSTAGES; s++) {
            const uint32_t mbar = sb + s * 8;
            const uint32_t dst  = sb + CTRL + s * STAGE_BYTES;
            MBAR_EXPECT_TX(mbar, STAGE_BYTES);
            bulk_g2s(dst,              Ag  + (size_t)s * TILE_B, TILE_B, mbar);
            bulk_g2s(dst + TILE_B,     B0g + (size_t)s * TILE_B, TILE_B, mbar);
            bulk_g2s(dst + 2 * TILE_B, B1g + (size_t)s * TILE_B, TILE_B, mbar);
        }
    }

    // per-thread ldmatrix addressing (constant swizzle component per thread)
    const int ra       = lid & 15;                    // A row offset within 16
    const uint32_t swa = (uint32_t)(ra & 7) << 4;
    const uint32_t csa = (uint32_t)(lid >> 4) << 4;   // 0 or 16 (k-byte select)
    const int rb       = (lid & 7) + ((lid >> 4) << 3); // B row offset within 16
    const uint32_t swb = (uint32_t)(rb & 7) << 4;
    const uint32_t csb = (uint32_t)((lid >> 3) & 1) << 4;
    const int wn_loc   = wn & 127;                    // row within 128-n tile
    const int btile    = wn >> 7;                     // which 16KB B tile

    float acc[4][8][4];
#pragma unroll
    for (int i = 0; i < 4; i++)
#pragma unroll
        for (int j = 0; j < 8; j++)
#pragma unroll
            for (int c = 0; c < 4; c++) acc[i][j][c] = 0.f;

    for (int kt = 0; kt < ktiles; kt++) {
        const int st = kt & (NSTAGES - 1);
        const int ph = (kt >> 2) & 1;
        MBAR_WAIT(sb + st * 8, ph);

        const uint32_t Abase = sb + CTRL + st * STAGE_BYTES;
        const uint32_t Bbase = Abase + TILE_B + btile * TILE_B;

#pragma unroll
        for (int ks = 0; ks < 4; ks++) {
            const uint32_t kb = ks * 32;
            uint32_t afrag[4][4];
            uint32_t bfrag[8][2];
#pragma unroll
            for (int mt = 0; mt < 4; mt++) {
                const int r = wm + mt * 16 + ra;
                ldsm_x4(afrag[mt], Abase + (uint32_t)r * 128 + ((kb + csa) ^ swa));
            }
#pragma unroll
            for (int q = 0; q < 4; q++) {
                const int n = wn_loc + q * 16 + rb;
                uint32_t t[4];
                ldsm_x4(t, Bbase + (uint32_t)n * 128 + ((kb + csb) ^ swb));
                bfrag[2 * q][0]     = t[0];
                bfrag[2 * q][1]     = t[1];
                bfrag[2 * q + 1][0] = t[2];
                bfrag[2 * q + 1][1] = t[3];
            }
#pragma unroll
            for (int mt = 0; mt < 4; mt++)
#pragma unroll
                for (int nt = 0; nt < 8; nt++)
                    mma16816(acc[mt][nt], afrag[mt], bfrag[nt]);
        }

        __syncthreads();   // all warps done reading stage st

        if (tid == 0 && kt + NSTAGES < ktiles) {
            const int j = kt + NSTAGES;
            const uint32_t mbar = sb + st * 8;
            const uint32_t dst  = sb + CTRL + st * STAGE_BYTES;
            MBAR_EXPECT_TX(mbar, STAGE_BYTES);
            bulk_g2s(dst,              Ag  + (size_t)j * TILE_B, TILE_B, mbar);
            bulk_g2s(dst + TILE_B,     B0g + (size_t)j * TILE_B, TILE_B, mbar);
            bulk_g2s(dst + 2 * TILE_B, B1g + (size_t)j * TILE_B, TILE_B, mbar);
        }
    }

    // ---- epilogue: h = f16(acc); h += f16(bias); out = f32(h) ----
    const int lr  = lid >> 2;
    const int lc2 = (lid & 3) * 2;
#pragma unroll
    for (int mt = 0; mt < 4; mt++) {
        const int row0 = m0 + wm + mt * 16 + lr;
        const int row1 = row0 + 8;
#pragma unroll
        for (int nt = 0; nt < 8; nt++) {
            const int col = n0 + wn + nt * 8 + lc2;
            const __half bh0 = __float2half_rn(__ldg(&bias[col]));
            const __half bh1 = __float2half_rn(__ldg(&bias[col + 1]));

            __half h00 = __hadd(__float2half_rn(acc[mt][nt][0]), bh0);
            __half h01 = __hadd(__float2half_rn(acc[mt][nt][1]), bh1);
            __half h10 = __hadd(__float2half_rn(acc[mt][nt][2]), bh0);
            __half h11 = __hadd(__float2half_rn(acc[mt][nt][3]), bh1);

            *(float2*)&out[(size_t)row0 * N + col] =
                make_float2(__half2float(h00), __half2float(h01));
            *(float2*)&out[(size_t)row1 * N + col] =
                make_float2(__half2float(h10), __half2float(h11));
        }
    }
}

// ------------------------- launcher --------------------------------
extern "C" void kernel_launch(void* const* d_in, const int* in_sizes, int n_in,
                              void* d_out, int out_size)
{
    const float* x     = (const float*)d_in[0];
    const int*   wq    = (const int*)d_in[1];
    const float* scale = (const float*)d_in[2];
    const float* bias  = (const float*)d_in[3];
    float*       out   = (float*)d_out;

    const int N = in_sizes[3];              // 11008
    const int K = in_sizes[1] / N;          // 4096
    const int M = in_sizes[0] / K;          // 2048

    const int ktiles = K / 64;
    const long wgroups = (long)(N / 128) * ktiles * 1024;
    const long xgroups = (long)(M / 128) * ktiles * 1024;

    prep_w<<<(unsigned)((wgroups + 255) / 256), 256>>>(wq, scale, K, wgroups);
    prep_x<<<(unsigned)((xgroups + 255) / 256), 256>>>(x, K, xgroups);

    static int smem_set = 0;
    if (!smem_set) {
        cudaFuncSetAttribute(qgemm, cudaFuncAttributeMaxDynamicSharedMemorySize, GEMM_SMEM);
        smem_set = 1;
    }
    dim3 grid(N / 256, M / 128);
    qgemm<<<grid, 256, GEMM_SMEM>>>(bias, out, M, N, K);
}